// round 16
// baseline (speedup 1.0000x reference)
#include <cuda_runtime.h>
#include <cuda_bf16.h>
#include <cuda_fp16.h>
#include <math_constants.h>
#include <cstdint>

#define D      256
#define K      1024
#define NROWS  65536
#define GM     64           // rows per gemm block
#define CAP    16
#define MARGIN 3.0e-3f
#define SCSTR  1032         // score smem stride (halfs)

__device__ float  g_cnorm[K];
__device__ double g_loss_sum;
__device__ __nv_bfloat16 g_cbf[K * D];       // bf16 codebook
__device__ unsigned short g_cand[NROWS * CAP];
__device__ int    g_ccnt[NROWS];

// ---------------------------------------------------------------------------
__device__ __forceinline__ void mma16816(float* c, const unsigned* a,
                                         unsigned b0, unsigned b1){
    asm volatile("mma.sync.aligned.m16n8k16.row.col.f32.bf16.bf16.f32 "
        "{%0,%1,%2,%3}, {%4,%5,%6,%7}, {%8,%9}, {%0,%1,%2,%3};"
        : "+f"(c[0]), "+f"(c[1]), "+f"(c[2]), "+f"(c[3])
        : "r"(a[0]), "r"(a[1]), "r"(a[2]), "r"(a[3]), "r"(b0), "r"(b1));
}

// ---------------------------------------------------------------------------
// Kernel 1: codebook norms (bit-exact) + cb->bf16 + zero loss. grid 128 x 256.
// ---------------------------------------------------------------------------
__global__ void k_setup(const float* __restrict__ cb){
    if (blockIdx.x == 0 && threadIdx.x == 0) g_loss_sum = 0.0;
    int w    = threadIdx.x >> 5;
    int lane = threadIdx.x & 31;
    int code = blockIdx.x * 8 + w;
    const float* c = cb + (size_t)code * D;
    float s = 0.f;
    #pragma unroll
    for (int j = 0; j < 8; j++){
        float v = c[lane + 32 * j];
        s = __fmaf_rn(v, v, s);
    }
    #pragma unroll
    for (int off = 16; off; off >>= 1)
        s += __shfl_xor_sync(0xffffffffu, s, off);
    if (lane == 0) g_cnorm[code] = s;

    int g = blockIdx.x * 256 + threadIdx.x;
    const float4* cb4 = (const float4*)cb;
    float4 x = cb4[g * 2], y = cb4[g * 2 + 1];
    __nv_bfloat162 p0 = __floats2bfloat162_rn(x.x, x.y);
    __nv_bfloat162 p1 = __floats2bfloat162_rn(x.z, x.w);
    __nv_bfloat162 p2 = __floats2bfloat162_rn(y.x, y.y);
    __nv_bfloat162 p3 = __floats2bfloat162_rn(y.z, y.w);
    uint4 o;
    o.x = *(unsigned*)&p0; o.y = *(unsigned*)&p1;
    o.z = *(unsigned*)&p2; o.w = *(unsigned*)&p3;
    ((uint4*)g_cbf)[g] = o;
}

// ---------------------------------------------------------------------------
// Kernel 2: bf16 HMMA approx scores + per-row min scan + candidate emission.
// (round-2 structure: 1 CTA/SM, 209KB smem, fused f32->bf16 A conversion)
// ---------------------------------------------------------------------------
__global__ __launch_bounds__(256, 1) void k_gemm(const float* __restrict__ Z){
    extern __shared__ __align__(16) unsigned char smraw[];
    __half*         sc    = (__half*)smraw;                          // 132096 B
    __nv_bfloat16*  sa    = (__nv_bfloat16*)(smraw + 132096);        //  33792 B
    __nv_bfloat16*  sb    = (__nv_bfloat16*)(smraw + 132096 + 33792);//  36864 B
    float*          cns   = (float*)(smraw + 202752);                //   4096 B
    unsigned short* candb = (unsigned short*)(smraw + 206848);       //   2048 B
    int*            cntb  = (int*)(smraw + 208896);                  //    256 B

    const int tid  = threadIdx.x;
    const int lane = tid & 31;
    const int w    = tid >> 5;
    const int gid  = lane >> 2;
    const int tig  = lane & 3;
    const int wm   = w >> 2;          // 0..1 -> row group
    const int wn   = w & 3;           // 0..3 -> code group
    const int row0 = blockIdx.x * GM;

    // --- load A tile (64 x 256): f32 -> bf16 fused conversion, padded smem ---
    {
        const float4* Z4 = (const float4*)(Z + (size_t)row0 * D);
        #pragma unroll
        for (int j = 0; j < 16; j++){
            int i = tid + 256 * j;        // 0..4095
            int r = i >> 6;               // row 0..63
            int f = i & 63;               // float4 within row
            float4 v = Z4[r * 64 + f];
            __nv_bfloat162 p0 = __floats2bfloat162_rn(v.x, v.y);
            __nv_bfloat162 p1 = __floats2bfloat162_rn(v.z, v.w);
            uint2 pv; pv.x = *(unsigned*)&p0; pv.y = *(unsigned*)&p1;
            *(uint2*)(sa + r * 264 + f * 4) = pv;
        }
    }
    #pragma unroll
    for (int j = 0; j < 4; j++) cns[tid + 256 * j] = g_cnorm[tid + 256 * j];
    if (tid < GM) cntb[tid] = 0;
    __syncthreads();

    const int4* cb4 = (const int4*)g_cbf;
    for (int ct = 0; ct < 4; ct++){
        float acc[2][8][4];
        #pragma unroll
        for (int m = 0; m < 2; m++)
            #pragma unroll
            for (int n = 0; n < 8; n++)
                #pragma unroll
                for (int q = 0; q < 4; q++) acc[m][n][q] = 0.f;

        for (int kc = 0; kc < 4; kc++){
            __syncthreads();
            // load B chunk: 256 codes x 64 halfs
            #pragma unroll
            for (int j = 0; j < 8; j++){
                int i    = tid + 256 * j;
                int code = i >> 3, c8 = i & 7;
                int4 v = cb4[(size_t)(ct * 256 + code) * 32 + kc * 8 + c8];
                *(int4*)(sb + code * 72 + c8 * 8) = v;
            }
            __syncthreads();

            #pragma unroll
            for (int ks = 0; ks < 4; ks++){
                int kb = kc * 64 + ks * 16;
                unsigned a[2][4];
                #pragma unroll
                for (int m = 0; m < 2; m++){
                    int ra = wm * 32 + m * 16 + gid;
                    const __nv_bfloat16* ap = sa + ra * 264 + kb + 2 * tig;
                    a[m][0] = *(const unsigned*)(ap);
                    a[m][1] = *(const unsigned*)(ap + 264 * 8);
                    a[m][2] = *(const unsigned*)(ap + 8);
                    a[m][3] = *(const unsigned*)(ap + 264 * 8 + 8);
                }
                #pragma unroll
                for (int n = 0; n < 8; n++){
                    int cbi = wn * 64 + n * 8 + gid;
                    const __nv_bfloat16* bp = sb + cbi * 72 + ks * 16 + 2 * tig;
                    unsigned b0 = *(const unsigned*)(bp);
                    unsigned b1 = *(const unsigned*)(bp + 8);
                    mma16816(acc[0][n], a[0], b0, b1);
                    mma16816(acc[1][n], a[1], b0, b1);
                }
            }
        }

        // epilogue: approx score = cn - 2*dot, store fp16
        #pragma unroll
        for (int m = 0; m < 2; m++){
            int r0 = wm * 32 + m * 16 + gid;
            #pragma unroll
            for (int n = 0; n < 8; n++){
                int col = ct * 256 + wn * 64 + n * 8 + 2 * tig;
                float c0 = cns[col], c1 = cns[col + 1];
                float s0 = c0 - 2.f * acc[m][n][0];
                float s1 = c1 - 2.f * acc[m][n][1];
                float s2 = c0 - 2.f * acc[m][n][2];
                float s3 = c1 - 2.f * acc[m][n][3];
                *(__half2*)(sc + r0 * SCSTR + col)       = __floats2half2_rn(s0, s1);
                *(__half2*)(sc + (r0 + 8) * SCSTR + col) = __floats2half2_rn(s2, s3);
            }
        }
    }
    __syncthreads();

    // --- per-row min scan + candidate emission (warp w: rows w*8 .. w*8+7) ---
    for (int rr = 0; rr < 8; rr++){
        int r = w * 8 + rr;
        const __half* srow = sc + r * SCSTR;
        float mn = CUDART_INF_F;
        #pragma unroll
        for (int j = 0; j < 32; j++)
            mn = fminf(mn, __half2float(srow[j * 32 + lane]));
        #pragma unroll
        for (int off = 16; off; off >>= 1)
            mn = fminf(mn, __shfl_xor_sync(0xffffffffu, mn, off));
        float thr = mn + MARGIN;
        #pragma unroll
        for (int j = 0; j < 32; j++){
            float vv = __half2float(srow[j * 32 + lane]);
            if (vv <= thr){
                int p = atomicAdd(&cntb[r], 1);
                if (p < CAP) candb[r * CAP + p] = (unsigned short)(j * 32 + lane);
            }
        }
    }
    __syncthreads();
    if (tid < GM) g_ccnt[row0 + tid] = cntb[tid];
    #pragma unroll
    for (int j = 0; j < 4; j++){
        int i = tid + 256 * j;   // 0..1023
        g_cand[(size_t)(row0 + (i >> 4)) * CAP + (i & 15)] = candb[i];
    }
}

// ---------------------------------------------------------------------------
// Kernel 3: exact rescore + fused gather/output/loss. 1 warp per row.
// FAST PATH: cnt==1 -> the lone candidate IS the argmin (margin-superset
// guarantee); skip zn + exact chain entirely. Exact ties always produce
// cnt>=2 (equal exact scores => approx scores within 2eps << margin), so the
// lexicographic bit-exact slow path still governs every tie.
// ---------------------------------------------------------------------------
__global__ __launch_bounds__(256) void k_rescore(
    const float* __restrict__ Z, const float* __restrict__ CB,
    float4* __restrict__ Oz, float* __restrict__ out_idx)
{
    __shared__ float szs[8][256];
    __shared__ float wsum[8];
    const int w    = threadIdx.x >> 5;
    const int lane = threadIdx.x & 31;
    const int row  = blockIdx.x * 8 + w;
    float* zr = szs[w];
    const float4* zr4 = (const float4*)zr;

    const float4* Z4 = (const float4*)(Z + (size_t)row * D);
    #pragma unroll
    for (int j = 0; j < 2; j++)
        *(float4*)(zr + (lane + 32 * j) * 4) = Z4[lane + 32 * j];
    __syncwarp();

    const int cnt = g_ccnt[row];
    const float4* CB4 = (const float4*)CB;
    int bi;

    if (cnt == 1){
        // unique candidate == argmin; no scoring needed
        bi = (int)g_cand[(size_t)row * CAP];
    } else {
        // zn: exact 8-accumulator pairwise-halving tree (bit-match reference)
        int l8 = lane & 7;
        float a = 0.f;
        #pragma unroll
        for (int i = 0; i < 32; i++){
            float x = zr[i * 8 + l8];
            a = __fadd_rn(a, __fmul_rn(x, x));
        }
        float aj  = __shfl_sync(0xffffffffu, a, lane & 3);
        float aj4 = __shfl_sync(0xffffffffu, a, (lane & 3) + 4);
        float b   = __fadd_rn(aj, aj4);
        float b0 = __shfl_sync(0xffffffffu, b, 0);
        float b1 = __shfl_sync(0xffffffffu, b, 1);
        float b2 = __shfl_sync(0xffffffffu, b, 2);
        float b3 = __shfl_sync(0xffffffffu, b, 3);
        float zn = __fadd_rn(__fadd_rn(b0, b2), __fadd_rn(b1, b3));

        float bs = CUDART_INF_F;
        bi = K;

        if (cnt <= CAP){
            if (lane < cnt){
                int ci = (int)g_cand[(size_t)row * CAP + lane];
                const float4* C4 = CB4 + (size_t)ci * 64;
                float dt = 0.f;
                #pragma unroll 16
                for (int q = 0; q < 64; q++){
                    float4 cv = C4[q];
                    float4 zv = zr4[q];
                    dt = __fmaf_rn(zv.x, cv.x, dt);
                    dt = __fmaf_rn(zv.y, cv.y, dt);
                    dt = __fmaf_rn(zv.z, cv.z, dt);
                    dt = __fmaf_rn(zv.w, cv.w, dt);
                }
                bs = __fmaf_rn(-2.0f, dt, __fadd_rn(zn, g_cnorm[ci]));
                bi = ci;
            }
        } else {
            // overflow fallback: full scan, 32 codes per lane
            for (int j = 0; j < 32; j++){
                int ci = j * 32 + lane;
                const float4* C4 = CB4 + (size_t)ci * 64;
                float dt = 0.f;
                #pragma unroll 16
                for (int q = 0; q < 64; q++){
                    float4 cv = C4[q];
                    float4 zv = zr4[q];
                    dt = __fmaf_rn(zv.x, cv.x, dt);
                    dt = __fmaf_rn(zv.y, cv.y, dt);
                    dt = __fmaf_rn(zv.z, cv.z, dt);
                    dt = __fmaf_rn(zv.w, cv.w, dt);
                }
                float s = __fmaf_rn(-2.0f, dt, __fadd_rn(zn, g_cnorm[ci]));
                if (s < bs || (s == bs && ci < bi)){ bs = s; bi = ci; }
            }
        }

        // lexicographic (score, index) min across warp
        #pragma unroll
        for (int off = 16; off; off >>= 1){
            float s2 = __shfl_xor_sync(0xffffffffu, bs, off);
            int   i2 = __shfl_xor_sync(0xffffffffu, bi, off);
            if (s2 < bs || (s2 == bs && i2 < bi)){ bs = s2; bi = i2; }
        }
    }

    // fused gather: z_q_st output + loss partial
    const float4* C4b = CB4 + (size_t)bi * 64;
    float lsum = 0.f;
    #pragma unroll
    for (int q = 0; q < 2; q++){
        int j = lane + 32 * q;
        float4 z = zr4[j];
        float4 qv = C4b[j];
        float d0 = __fsub_rn(qv.x, z.x);
        float d1 = __fsub_rn(qv.y, z.y);
        float d2 = __fsub_rn(qv.z, z.z);
        float d3 = __fsub_rn(qv.w, z.w);
        float4 o;
        o.x = __fadd_rn(z.x, d0);
        o.y = __fadd_rn(z.y, d1);
        o.z = __fadd_rn(z.z, d2);
        o.w = __fadd_rn(z.w, d3);
        Oz[(size_t)row * 64 + j] = o;
        lsum += d0 * d0 + d1 * d1 + d2 * d2 + d3 * d3;
    }
    #pragma unroll
    for (int off = 16; off; off >>= 1)
        lsum += __shfl_xor_sync(0xffffffffu, lsum, off);
    if (lane == 0){
        wsum[w] = lsum;
        out_idx[row] = (float)bi;
    }
    __syncthreads();
    if (threadIdx.x == 0){
        float bsum = 0.f;
        #pragma unroll
        for (int i = 0; i < 8; i++) bsum += wsum[i];
        atomicAdd(&g_loss_sum, (double)bsum);
    }
}

// ---------------------------------------------------------------------------
__global__ void k_loss(float* __restrict__ out_loss, int n_total){
    double m  = g_loss_sum / (double)n_total;
    float  cb = (float)m;
    out_loss[0] = __fadd_rn(cb, __fmul_rn(0.25f, cb));
}

// ---------------------------------------------------------------------------
extern "C" void kernel_launch(void* const* d_in, const int* in_sizes, int n_in,
                              void* d_out, int out_size)
{
    const float* Z  = (const float*)d_in[0];
    const float* CB = (const float*)d_in[1];
    float* out = (float*)d_out;
    const int n_z = in_sizes[0];      // 16777216
    const int N   = n_z >> 8;         // 65536 rows

    k_setup<<<128, 256>>>(CB);

    const int smem = 209152;
    cudaFuncSetAttribute(k_gemm, cudaFuncAttributeMaxDynamicSharedMemorySize, smem);
    k_gemm<<<N / GM, 256, smem>>>(Z);

    // out layout: [ z_q_st (n_z) | vq_loss (1) | indices (N) ]
    k_rescore<<<N / 8, 256>>>(Z, CB, (float4*)out, out + n_z + 1);

    k_loss<<<1, 1>>>(out + n_z, n_z);
}

// round 17
// speedup vs baseline: 1.1827x; 1.1827x over previous
#include <cuda_runtime.h>
#include <cuda_bf16.h>
#include <cuda_fp16.h>
#include <math_constants.h>
#include <cstdint>

#define D      256
#define K      1024
#define NROWS  65536
#define GM     64           // rows per gemm block
#define CAP    16
#define MARGIN 3.0e-3f
#define SCSTR  1032         // score smem stride (halfs)

__device__ float  g_cnorm[K];
__device__ double g_loss_sum;
__device__ __nv_bfloat16 g_cbf[K * D];       // bf16 codebook

// ---------------------------------------------------------------------------
__device__ __forceinline__ void mma16816(float* c, const unsigned* a,
                                         unsigned b0, unsigned b1){
    asm volatile("mma.sync.aligned.m16n8k16.row.col.f32.bf16.bf16.f32 "
        "{%0,%1,%2,%3}, {%4,%5,%6,%7}, {%8,%9}, {%0,%1,%2,%3};"
        : "+f"(c[0]), "+f"(c[1]), "+f"(c[2]), "+f"(c[3])
        : "r"(a[0]), "r"(a[1]), "r"(a[2]), "r"(a[3]), "r"(b0), "r"(b1));
}

// ---------------------------------------------------------------------------
// Kernel 1: codebook norms (bit-exact) + cb->bf16 + zero loss. grid 128 x 256.
// ---------------------------------------------------------------------------
__global__ void k_setup(const float* __restrict__ cb){
    if (blockIdx.x == 0 && threadIdx.x == 0) g_loss_sum = 0.0;
    int w    = threadIdx.x >> 5;
    int lane = threadIdx.x & 31;
    int code = blockIdx.x * 8 + w;
    const float* c = cb + (size_t)code * D;
    float s = 0.f;
    #pragma unroll
    for (int j = 0; j < 8; j++){
        float v = c[lane + 32 * j];
        s = __fmaf_rn(v, v, s);
    }
    #pragma unroll
    for (int off = 16; off; off >>= 1)
        s += __shfl_xor_sync(0xffffffffu, s, off);
    if (lane == 0) g_cnorm[code] = s;

    int g = blockIdx.x * 256 + threadIdx.x;
    const float4* cb4 = (const float4*)cb;
    float4 x = cb4[g * 2], y = cb4[g * 2 + 1];
    __nv_bfloat162 p0 = __floats2bfloat162_rn(x.x, x.y);
    __nv_bfloat162 p1 = __floats2bfloat162_rn(x.z, x.w);
    __nv_bfloat162 p2 = __floats2bfloat162_rn(y.x, y.y);
    __nv_bfloat162 p3 = __floats2bfloat162_rn(y.z, y.w);
    uint4 o;
    o.x = *(unsigned*)&p0; o.y = *(unsigned*)&p1;
    o.z = *(unsigned*)&p2; o.w = *(unsigned*)&p3;
    ((uint4*)g_cbf)[g] = o;
}

// ---------------------------------------------------------------------------
// Kernel 2: FULLY FUSED. bf16 HMMA approx scores (round-2/15 schedule,
// 1 CTA/SM, 209KB smem, fused f32->bf16 A conversion) + per-row min scan +
// candidate emission + IN-KERNEL exact rescore (bit-exact round-0 arithmetic,
// candidate-per-lane, lexicographic tie-break, cnt==1 fast path) + fused
// gather / z_q_st output / loss accumulation.
// ---------------------------------------------------------------------------
__global__ __launch_bounds__(256, 1) void k_gemm(
    const float* __restrict__ Z, const float* __restrict__ CB,
    float4* __restrict__ Oz, float* __restrict__ out_idx)
{
    extern __shared__ __align__(16) unsigned char smraw[];
    __half*         sc    = (__half*)smraw;                          // 132096 B
    __nv_bfloat16*  sa    = (__nv_bfloat16*)(smraw + 132096);        //  33792 B
    __nv_bfloat16*  sb    = (__nv_bfloat16*)(smraw + 132096 + 33792);//  36864 B
    float*          cns   = (float*)(smraw + 202752);                //   4096 B
    unsigned short* candb = (unsigned short*)(smraw + 206848);       //   2048 B
    int*            cntb  = (int*)(smraw + 208896);                  //    256 B
    float*          wsum  = (float*)(smraw + 209152);                //     32 B
    // per-warp f32 z-row scratch, aliased onto dead A region after mma phase
    float*          zscr  = (float*)(smraw + 132096);                //   8 KB

    const int tid  = threadIdx.x;
    const int lane = tid & 31;
    const int w    = tid >> 5;
    const int gid  = lane >> 2;
    const int tig  = lane & 3;
    const int wm   = w >> 2;          // 0..1 -> row group
    const int wn   = w & 3;           // 0..3 -> code group
    const int row0 = blockIdx.x * GM;

    // --- load A tile (64 x 256): f32 -> bf16 fused conversion, padded smem ---
    {
        const float4* Z4 = (const float4*)(Z + (size_t)row0 * D);
        #pragma unroll
        for (int j = 0; j < 16; j++){
            int i = tid + 256 * j;        // 0..4095
            int r = i >> 6;               // row 0..63
            int f = i & 63;               // float4 within row
            float4 v = Z4[r * 64 + f];
            __nv_bfloat162 p0 = __floats2bfloat162_rn(v.x, v.y);
            __nv_bfloat162 p1 = __floats2bfloat162_rn(v.z, v.w);
            uint2 pv; pv.x = *(unsigned*)&p0; pv.y = *(unsigned*)&p1;
            *(uint2*)(sa + r * 264 + f * 4) = pv;
        }
    }
    #pragma unroll
    for (int j = 0; j < 4; j++) cns[tid + 256 * j] = g_cnorm[tid + 256 * j];
    if (tid < GM) cntb[tid] = 0;
    __syncthreads();

    const int4* cb4 = (const int4*)g_cbf;
    for (int ct = 0; ct < 4; ct++){
        float acc[2][8][4];
        #pragma unroll
        for (int m = 0; m < 2; m++)
            #pragma unroll
            for (int n = 0; n < 8; n++)
                #pragma unroll
                for (int q = 0; q < 4; q++) acc[m][n][q] = 0.f;

        for (int kc = 0; kc < 4; kc++){
            __syncthreads();
            // load B chunk: 256 codes x 64 halfs
            #pragma unroll
            for (int j = 0; j < 8; j++){
                int i    = tid + 256 * j;
                int code = i >> 3, c8 = i & 7;
                int4 v = cb4[(size_t)(ct * 256 + code) * 32 + kc * 8 + c8];
                *(int4*)(sb + code * 72 + c8 * 8) = v;
            }
            __syncthreads();

            #pragma unroll
            for (int ks = 0; ks < 4; ks++){
                int kb = kc * 64 + ks * 16;
                unsigned a[2][4];
                #pragma unroll
                for (int m = 0; m < 2; m++){
                    int ra = wm * 32 + m * 16 + gid;
                    const __nv_bfloat16* ap = sa + ra * 264 + kb + 2 * tig;
                    a[m][0] = *(const unsigned*)(ap);
                    a[m][1] = *(const unsigned*)(ap + 264 * 8);
                    a[m][2] = *(const unsigned*)(ap + 8);
                    a[m][3] = *(const unsigned*)(ap + 264 * 8 + 8);
                }
                #pragma unroll
                for (int n = 0; n < 8; n++){
                    int cbi = wn * 64 + n * 8 + gid;
                    const __nv_bfloat16* bp = sb + cbi * 72 + ks * 16 + 2 * tig;
                    unsigned b0 = *(const unsigned*)(bp);
                    unsigned b1 = *(const unsigned*)(bp + 8);
                    mma16816(acc[0][n], a[0], b0, b1);
                    mma16816(acc[1][n], a[1], b0, b1);
                }
            }
        }

        // epilogue: approx score = cn - 2*dot (zn-free: rank-equivalent), fp16
        #pragma unroll
        for (int m = 0; m < 2; m++){
            int r0 = wm * 32 + m * 16 + gid;
            #pragma unroll
            for (int n = 0; n < 8; n++){
                int col = ct * 256 + wn * 64 + n * 8 + 2 * tig;
                float c0 = cns[col], c1 = cns[col + 1];
                float s0 = c0 - 2.f * acc[m][n][0];
                float s1 = c1 - 2.f * acc[m][n][1];
                float s2 = c0 - 2.f * acc[m][n][2];
                float s3 = c1 - 2.f * acc[m][n][3];
                *(__half2*)(sc + r0 * SCSTR + col)       = __floats2half2_rn(s0, s1);
                *(__half2*)(sc + (r0 + 8) * SCSTR + col) = __floats2half2_rn(s2, s3);
            }
        }
    }
    __syncthreads();   // mma phase done: sa region now reusable as z scratch

    // --- per-row min scan + candidate emission (warp w: rows w*8 .. w*8+7) ---
    for (int rr = 0; rr < 8; rr++){
        int r = w * 8 + rr;
        const __half* srow = sc + r * SCSTR;
        float mn = CUDART_INF_F;
        #pragma unroll
        for (int j = 0; j < 32; j++)
            mn = fminf(mn, __half2float(srow[j * 32 + lane]));
        #pragma unroll
        for (int off = 16; off; off >>= 1)
            mn = fminf(mn, __shfl_xor_sync(0xffffffffu, mn, off));
        float thr = mn + MARGIN;
        #pragma unroll
        for (int j = 0; j < 32; j++){
            float vv = __half2float(srow[j * 32 + lane]);
            if (vv <= thr){
                int p = atomicAdd(&cntb[r], 1);
                if (p < CAP) candb[r * CAP + p] = (unsigned short)(j * 32 + lane);
            }
        }
    }
    // no block sync needed: each row's cnt/cand written and read by same warp

    // --- fused exact rescore + gather + output + loss (warp w: its 8 rows) ---
    const float4* CB4 = (const float4*)CB;
    float* zr = zscr + w * 256;
    const float4* zr4 = (const float4*)zr;
    float lacc = 0.f;

    for (int rr = 0; rr < 8; rr++){
        int r   = w * 8 + rr;
        int row = row0 + r;

        // stage f32 z row (L2-hot: block read it at start)
        const float4* Z4r = (const float4*)(Z + (size_t)row * D);
        *(float4*)(zr + lane * 4)            = Z4r[lane];
        *(float4*)(zr + (lane + 32) * 4)     = Z4r[lane + 32];
        __syncwarp();

        const int cnt = cntb[r];
        int bi;

        if (cnt == 1){
            bi = (int)candb[r * CAP];
        } else {
            // zn: exact 8-accumulator pairwise-halving tree (bit-match ref)
            int l8 = lane & 7;
            float a = 0.f;
            #pragma unroll
            for (int i = 0; i < 32; i++){
                float x = zr[i * 8 + l8];
                a = __fadd_rn(a, __fmul_rn(x, x));
            }
            float aj  = __shfl_sync(0xffffffffu, a, lane & 3);
            float aj4 = __shfl_sync(0xffffffffu, a, (lane & 3) + 4);
            float b   = __fadd_rn(aj, aj4);
            float b0 = __shfl_sync(0xffffffffu, b, 0);
            float b1 = __shfl_sync(0xffffffffu, b, 1);
            float b2 = __shfl_sync(0xffffffffu, b, 2);
            float b3 = __shfl_sync(0xffffffffu, b, 3);
            float zn = __fadd_rn(__fadd_rn(b0, b2), __fadd_rn(b1, b3));

            float bs = CUDART_INF_F;
            bi = K;
            if (cnt <= CAP){
                if (lane < cnt){
                    int ci = (int)candb[r * CAP + lane];
                    const float4* C4 = CB4 + (size_t)ci * 64;
                    float dt = 0.f;
                    #pragma unroll 16
                    for (int q = 0; q < 64; q++){
                        float4 cv = C4[q];
                        float4 zv = zr4[q];
                        dt = __fmaf_rn(zv.x, cv.x, dt);
                        dt = __fmaf_rn(zv.y, cv.y, dt);
                        dt = __fmaf_rn(zv.z, cv.z, dt);
                        dt = __fmaf_rn(zv.w, cv.w, dt);
                    }
                    bs = __fmaf_rn(-2.0f, dt, __fadd_rn(zn, g_cnorm[ci]));
                    bi = ci;
                }
            } else {
                // overflow fallback: full scan, 32 codes per lane
                for (int j = 0; j < 32; j++){
                    int ci = j * 32 + lane;
                    const float4* C4 = CB4 + (size_t)ci * 64;
                    float dt = 0.f;
                    #pragma unroll 16
                    for (int q = 0; q < 64; q++){
                        float4 cv = C4[q];
                        float4 zv = zr4[q];
                        dt = __fmaf_rn(zv.x, cv.x, dt);
                        dt = __fmaf_rn(zv.y, cv.y, dt);
                        dt = __fmaf_rn(zv.z, cv.z, dt);
                        dt = __fmaf_rn(zv.w, cv.w, dt);
                    }
                    float s = __fmaf_rn(-2.0f, dt, __fadd_rn(zn, g_cnorm[ci]));
                    if (s < bs || (s == bs && ci < bi)){ bs = s; bi = ci; }
                }
            }
            // lexicographic (score, index) min across warp
            #pragma unroll
            for (int off = 16; off; off >>= 1){
                float s2 = __shfl_xor_sync(0xffffffffu, bs, off);
                int   i2 = __shfl_xor_sync(0xffffffffu, bi, off);
                if (s2 < bs || (s2 == bs && i2 < bi)){ bs = s2; bi = i2; }
            }
        }

        // fused gather: z_q_st output + loss partial
        const float4* C4b = CB4 + (size_t)bi * 64;
        #pragma unroll
        for (int q = 0; q < 2; q++){
            int j = lane + 32 * q;
            float4 z = zr4[j];
            float4 qv = C4b[j];
            float d0 = __fsub_rn(qv.x, z.x);
            float d1 = __fsub_rn(qv.y, z.y);
            float d2 = __fsub_rn(qv.z, z.z);
            float d3 = __fsub_rn(qv.w, z.w);
            float4 o;
            o.x = __fadd_rn(z.x, d0);
            o.y = __fadd_rn(z.y, d1);
            o.z = __fadd_rn(z.z, d2);
            o.w = __fadd_rn(z.w, d3);
            Oz[(size_t)row * 64 + j] = o;
            lacc += d0 * d0 + d1 * d1 + d2 * d2 + d3 * d3;
        }
        if (lane == 0) out_idx[row] = (float)bi;
        __syncwarp();   // zr reuse safe for next row
    }

    // loss: warp reduce -> block reduce -> one atomicAdd
    #pragma unroll
    for (int off = 16; off; off >>= 1)
        lacc += __shfl_xor_sync(0xffffffffu, lacc, off);
    if (lane == 0) wsum[w] = lacc;
    __syncthreads();
    if (tid == 0){
        float bsum = 0.f;
        #pragma unroll
        for (int i = 0; i < 8; i++) bsum += wsum[i];
        atomicAdd(&g_loss_sum, (double)bsum);
    }
}

// ---------------------------------------------------------------------------
__global__ void k_loss(float* __restrict__ out_loss, int n_total){
    double m  = g_loss_sum / (double)n_total;
    float  cb = (float)m;
    out_loss[0] = __fadd_rn(cb, __fmul_rn(0.25f, cb));
}

// ---------------------------------------------------------------------------
extern "C" void kernel_launch(void* const* d_in, const int* in_sizes, int n_in,
                              void* d_out, int out_size)
{
    const float* Z  = (const float*)d_in[0];
    const float* CB = (const float*)d_in[1];
    float* out = (float*)d_out;
    const int n_z = in_sizes[0];      // 16777216
    const int N   = n_z >> 8;         // 65536 rows

    k_setup<<<128, 256>>>(CB);

    const int smem = 209184;
    cudaFuncSetAttribute(k_gemm, cudaFuncAttributeMaxDynamicSharedMemorySize, smem);
    // out layout: [ z_q_st (n_z) | vq_loss (1) | indices (N) ]
    k_gemm<<<N / GM, 256, smem>>>(Z, CB, (float4*)out, out + n_z + 1);

    k_loss<<<1, 1>>>(out + n_z, n_z);
}